// round 14
// baseline (speedup 1.0000x reference)
#include <cuda_runtime.h>
#include <cstdint>

#define M_PTS 5151
#define HIDN  256
#define BB    16
#define SS    256
#define TT    1024
#define GRID_N 101
#define TDIM   16
#define NTILES 28          // 7x7 upper-triangular tiles of 16x16
#define TC     64          // scan time-chunk
#define TSTR   68          // tile row stride (floats, 16B aligned)
#define CUT 0.018f

// k_mlp smem (words): Xh_p/Xl_p 32x132 uint32 each; Bh_p/Bl_p 8x264 each
#define XP_STR 132
#define BP_STR 264
#define SM_XH 0
#define SM_XL (32*XP_STR)
#define SM_BH (2*32*XP_STR)
#define SM_BL (2*32*XP_STR + 8*BP_STR)
#define MLP_SMEM_WORDS (2*32*XP_STR + 2*8*BP_STR)
#define MLP_SMEM_BYTES (MLP_SMEM_WORDS*4)           // 50688

#define OFF_BOUT 0
#define OFF_D    16384
#define OFF_M    (OFF_D + BB*M_PTS)
#define OFF_IS   (OFF_M + BB*TT)
#define OFF_MESH (OFF_IS + BB*M_PTS)

// ---------------- scratch ----------------
__device__ uint32_t g_wph[3*128*HIDN];
__device__ uint32_t g_wpl[3*128*HIDN];
__device__ float g_density[M_PTS];
__device__ float g_cwc[BB*HIDN];
__device__ float g_init[BB*M_PTS];
__device__ float g_bpart[BB*NTILES*TT];

__device__ __forceinline__ float fast_tanh(float x) {
    float r;
    asm("tanh.approx.f32 %0, %1;" : "=f"(r) : "f"(x));
    return r;
}

__device__ __forceinline__ float bf16lo_f(uint32_t p) {
    return __uint_as_float(p << 16);
}
__device__ __forceinline__ float bf16hi_f(uint32_t p) {
    return __uint_as_float(p & 0xffff0000u);
}
__device__ __forceinline__ uint32_t pack_split(float x0, float x1, uint32_t* lo) {
    uint32_t hp;
    asm("cvt.rn.bf16x2.f32 %0, %1, %2;" : "=r"(hp) : "f"(x1), "f"(x0));
    float h0 = bf16lo_f(hp), h1 = bf16hi_f(hp);
    uint32_t lp;
    asm("cvt.rn.bf16x2.f32 %0, %1, %2;" : "=r"(lp) : "f"(x1 - h1), "f"(x0 - h0));
    *lo = lp;
    return hp;
}

__device__ __forceinline__ void mma_bf16(float* c, const uint32_t* a, const uint32_t* b) {
    asm volatile(
        "mma.sync.aligned.m16n8k16.row.col.f32.bf16.bf16.f32 "
        "{%0,%1,%2,%3}, {%4,%5,%6,%7}, {%8,%9}, {%0,%1,%2,%3};"
        : "+f"(c[0]), "+f"(c[1]), "+f"(c[2]), "+f"(c[3])
        : "r"(a[0]), "r"(a[1]), "r"(a[2]), "r"(a[3]),
          "r"(b[0]), "r"(b[1]));
}

// ---------------- W split+pack (once) ----------------
__global__ void k_wsplitp(const float* __restrict__ Wr) {
    int i = blockIdx.x*256 + threadIdx.x;
    if (i >= 3*128*HIDN) return;
    int l  = i >> 15;
    int r2 = (i >> 8) & 127;
    int n  = i & 255;
    const float* base = Wr + l*HIDN*HIDN;
    float w0 = base[(2*r2  )*HIDN + n];
    float w1 = base[(2*r2+1)*HIDN + n];
    uint32_t lo;
    uint32_t hi = pack_split(w0, w1, &lo);
    g_wph[i] = hi;
    g_wpl[i] = lo;
}

// ===== fused density MLP: dens_in + 3 res layers (bf16 3-term) + dens_out ==
__global__ void __launch_bounds__(256) k_mlp(
    const float* __restrict__ mesh,
    const float* __restrict__ Win, const float* __restrict__ bin,
    const float* __restrict__ br,
    const float* __restrict__ Wout, const float* __restrict__ bout)
{
    extern __shared__ __align__(16) uint32_t smw[];
    uint32_t* Xh = smw + SM_XH;
    uint32_t* Xl = smw + SM_XL;
    uint32_t* Bh = smw + SM_BH;
    uint32_t* Bl = smw + SM_BL;

    int tid = threadIdx.x;
    int bm = blockIdx.x * 32;

    {
        int r  = tid >> 3;
        int c0 = (tid & 7) * 32;
        int gr = bm + r;
        bool ok = gr < M_PTS;
        float be = ok ? mesh[2*gr]   : 0.f;
        float al = ok ? mesh[2*gr+1] : 0.f;
#pragma unroll 4
        for (int p = 0; p < 16; p++) {
            int c = c0 + 2*p;
            float x0 = ok ? fmaxf(be*Win[c]   + al*Win[HIDN+c]   + bin[c],   0.f) : 0.f;
            float x1 = ok ? fmaxf(be*Win[c+1] + al*Win[HIDN+c+1] + bin[c+1], 0.f) : 0.f;
            uint32_t lo;
            uint32_t hi = pack_split(x0, x1, &lo);
            Xh[r*XP_STR + (c>>1)] = hi;
            Xl[r*XP_STR + (c>>1)] = lo;
        }
    }
    __syncthreads();

    int warp = tid >> 5, lane = tid & 31;
    int lr = lane >> 2, lc = lane & 3;
    int n_base = warp * 32;

    int woff = tid * 8;
    int wr2  = woff >> 8;
    int wcc  = woff & 255;

    for (int layer = 0; layer < 3; layer++) {
        const uint32_t* WPH = g_wph + layer*128*HIDN;
        const uint32_t* WPL = g_wpl + layer*128*HIDN;
        const float* bias = br + layer*HIDN;

        float acc[2][4][4];
#pragma unroll
        for (int t = 0; t < 2; t++)
#pragma unroll
            for (int j = 0; j < 4; j++)
#pragma unroll
                for (int q = 0; q < 4; q++) acc[t][j][q] = 0.f;

        uint4 ph0 = *(const uint4*)&WPH[woff];
        uint4 ph1 = *(const uint4*)&WPH[woff + 4];
        uint4 pl0 = *(const uint4*)&WPL[woff];
        uint4 pl1 = *(const uint4*)&WPL[woff + 4];

        for (int ch = 0; ch < 16; ch++) {
            *(uint4*)&Bh[wr2*BP_STR + wcc]     = ph0;
            *(uint4*)&Bh[wr2*BP_STR + wcc + 4] = ph1;
            *(uint4*)&Bl[wr2*BP_STR + wcc]     = pl0;
            *(uint4*)&Bl[wr2*BP_STR + wcc + 4] = pl1;
            __syncthreads();

            if (ch < 15) {
                int g = (ch + 1)*2048 + woff;
                ph0 = *(const uint4*)&WPH[g];
                ph1 = *(const uint4*)&WPH[g + 4];
                pl0 = *(const uint4*)&WPL[g];
                pl1 = *(const uint4*)&WPL[g + 4];
            }

            int k2b = ch * 8;
            uint32_t a_h[2][4], a_l[2][4];
#pragma unroll
            for (int t = 0; t < 2; t++) {
                int r = t*16 + lr;
                a_h[t][0] = Xh[ r     *XP_STR + k2b + lc];
                a_h[t][1] = Xh[(r + 8)*XP_STR + k2b + lc];
                a_h[t][2] = Xh[ r     *XP_STR + k2b + lc + 4];
                a_h[t][3] = Xh[(r + 8)*XP_STR + k2b + lc + 4];
                a_l[t][0] = Xl[ r     *XP_STR + k2b + lc];
                a_l[t][1] = Xl[(r + 8)*XP_STR + k2b + lc];
                a_l[t][2] = Xl[ r     *XP_STR + k2b + lc + 4];
                a_l[t][3] = Xl[(r + 8)*XP_STR + k2b + lc + 4];
            }
            uint32_t b_h[4][2], b_l[4][2];
#pragma unroll
            for (int j = 0; j < 4; j++) {
                int n = n_base + j*8 + lr;
                b_h[j][0] = Bh[ lc     *BP_STR + n];
                b_h[j][1] = Bh[(lc + 4)*BP_STR + n];
                b_l[j][0] = Bl[ lc     *BP_STR + n];
                b_l[j][1] = Bl[(lc + 4)*BP_STR + n];
            }
#pragma unroll
            for (int t = 0; t < 2; t++)
#pragma unroll
                for (int j = 0; j < 4; j++) {
                    mma_bf16(acc[t][j], a_h[t], b_h[j]);
                    mma_bf16(acc[t][j], a_h[t], b_l[j]);
                    mma_bf16(acc[t][j], a_l[t], b_h[j]);
                }
            __syncthreads();
        }

#pragma unroll
        for (int t = 0; t < 2; t++)
#pragma unroll
            for (int j = 0; j < 4; j++) {
                int c = n_base + j*8 + 2*lc;
                int c2 = c >> 1;
                float2 bz = *(const float2*)&bias[c];
#pragma unroll
                for (int h = 0; h < 2; h++) {
                    int r = t*16 + lr + 8*h;
                    int g = r*XP_STR + c2;
                    uint32_t hp = Xh[g], lp = Xl[g];
                    float x0 = bf16lo_f(hp) + bf16lo_f(lp);
                    float x1 = bf16hi_f(hp) + bf16hi_f(lp);
                    float y0 = x0 + fmaxf(acc[t][j][2*h]   + bz.x, 0.f);
                    float y1 = x1 + fmaxf(acc[t][j][2*h+1] + bz.y, 0.f);
                    uint32_t lo;
                    Xh[g] = pack_split(y0, y1, &lo);
                    Xl[g] = lo;
                }
            }
        __syncthreads();
    }

    {
        float b0 = bout[0];
#pragma unroll
        for (int rr = 0; rr < 4; rr++) {
            int r = warp*4 + rr;
            int gr = bm + r;
            float a = 0.f;
#pragma unroll
            for (int i = 0; i < 4; i++) {
                int c2 = lane + i*32;
                uint32_t hp = Xh[r*XP_STR + c2], lp = Xl[r*XP_STR + c2];
                a += (bf16lo_f(hp) + bf16lo_f(lp)) * Wout[2*c2];
                a += (bf16hi_f(hp) + bf16hi_f(lp)) * Wout[2*c2+1];
            }
#pragma unroll
            for (int o = 16; o; o >>= 1) a += __shfl_xor_sync(0xffffffffu, a, o);
            if (lane == 0 && gr < M_PTS)
                g_density[gr] = 1.f / (1.f + __expf(-(a + b0)));
        }
    }
}

// ---------------- encoder ctx + ctx @ Wc ----------------
__global__ void k_ctxw(const float* __restrict__ enc,
                       const float* __restrict__ mask,
                       const float* __restrict__ Ws,
                       const float* __restrict__ bs,
                       const float* __restrict__ Wc) {
    int b = blockIdx.x;
    int j = threadIdx.x;
    __shared__ float se[2*SS];
    __shared__ float sm[SS];
    __shared__ float sctx[HIDN];
    for (int i = j; i < 2*SS; i += 256) se[i] = enc[b*2*SS + i];
    for (int i = j; i < SS;   i += 256) sm[i] = mask[b*SS + i];
    __syncthreads();
    float w0 = Ws[j], w1 = Ws[HIDN + j], bj = bs[j];
    float acc = 0.f, msum = 0.f;
    for (int s = 0; s < SS; s++) {
        float mk = sm[s];
        msum += mk;
        float v = fmaxf(se[2*s]*w0 + se[2*s+1]*w1 + bj, 0.f);
        acc += mk * v;
    }
    sctx[j] = acc / fmaxf(msum, 1.f);
    __syncthreads();
    float a2 = 0.f;
    for (int k = 0; k < HIDN; k++) a2 += sctx[k] * Wc[k*HIDN + j];
    g_cwc[b*HIDN + j] = a2;
}

// ------- initial states, batch-major: block = 32 m-points x 16 batches ----
// thread = (m, j-strip); j strided by 8 for conflict-free smem access.
__global__ void __launch_bounds__(256) k_init(
    const float* __restrict__ mesh,
    const float* __restrict__ Wm,
    const float* __restrict__ bm,
    const float* __restrict__ Wo,
    const float* __restrict__ bo,
    float* __restrict__ out)
{
    __shared__ __align__(16) float4 sW[HIDN];        // (w0,w1,w2,wo)
    __shared__ float sC[BB*HIDN];                    // cwc + bm
    int tid = threadIdx.x;

    {
        sW[tid] = make_float4(Wm[tid], Wm[HIDN + tid], Wm[2*HIDN + tid], Wo[tid]);
        float bmj = bm[tid];
#pragma unroll
        for (int b = 0; b < BB; b++)
            sC[b*HIDN + tid] = g_cwc[b*HIDN + tid] + bmj;
    }
    __syncthreads();

    int ml = tid >> 3;            // 0..31
    int strip = tid & 7;          // 0..7
    int m = blockIdx.x*32 + ml;
    bool ok = m < M_PTS;
    int mm = ok ? m : 0;
    float be = mesh[2*mm], al = mesh[2*mm+1], d = g_density[mm];

    float acc[BB];
#pragma unroll
    for (int b = 0; b < BB; b++) acc[b] = 0.f;

    for (int jj = 0; jj < 32; jj++) {
        int j = strip + 8*jj;
        float4 w = sW[j];
        float P = be*w.x + al*w.y + d*w.z;
        float wo = w.w;
#pragma unroll
        for (int b = 0; b < BB; b++)
            acc[b] += fmaxf(P + sC[b*HIDN + j], 0.f) * wo;
    }

    // reduce across the 8 strips (adjacent lanes)
#pragma unroll
    for (int b = 0; b < BB; b++) {
        acc[b] += __shfl_xor_sync(0xffffffffu, acc[b], 1);
        acc[b] += __shfl_xor_sync(0xffffffffu, acc[b], 2);
        acc[b] += __shfl_xor_sync(0xffffffffu, acc[b], 4);
    }

    if (strip == 0 && ok) {
        float bo0 = bo[0];
#pragma unroll
        for (int b = 0; b < BB; b++) {
            float is = tanhf(acc[b] + bo0);
            g_init[b*M_PTS + m] = is;
            out[OFF_IS + (size_t)b*M_PTS + m] = is;
            out[OFF_D  + (size_t)b*M_PTS + m] = d;
            ((float2*)out)[(OFF_MESH >> 1) + (size_t)b*M_PTS + m] = make_float2(be, al);
        }
    }
}

// ------- relay scan: 16beta x 16alpha tiles, 128 thr, 2 beta pts/thread ---
// TC=64 chunks; float4 reduce (rows rg+8i, 4-col groups; bank-verified).
__global__ void __launch_bounds__(128) k_scan(const float* __restrict__ dec,
                                              const float* __restrict__ mesh) {
    __shared__ __align__(16) float sh_h[TT];
    __shared__ __align__(16) float tile[128*TSTR];
    __shared__ __align__(16) float aux[8*TSTR];
    int b = blockIdx.y;
    int tid = threadIdx.x;        // 0..127

    int tb = 0, rem = blockIdx.x;
    while (rem >= 7 - tb) { rem -= 7 - tb; tb++; }
    int ta = tb + rem;

    int ib0 = tb*TDIM + 2*(tid >> 4);
    int ib1 = ib0 + 1;
    int ia  = ta*TDIM + (tid & 15);
    bool v0 = (ib0 <= ia) && (ib0 < GRID_N) && (ia < GRID_N);
    bool v1 = (ib1 <= ia) && (ib1 < GRID_N) && (ia < GRID_N);
    int idx0 = v0 ? (ib0*GRID_N - (ib0*(ib0-1))/2 + ia - ib0) : 0;
    int idx1 = v1 ? (ib1*GRID_N - (ib1*(ib1-1))/2 + ia - ib1) : 0;

    for (int t = tid; t < TT; t += 128) sh_h[t] = dec[b*TT + t];

    float al  = v0 ? mesh[2*idx0 + 1] : (v1 ? mesh[2*idx1 + 1] : 2.f);
    float be0 = v0 ? mesh[2*idx0]     : -2.f;
    float be1 = v1 ? mesh[2*idx1]     : -2.f;
    float d0  = v0 ? g_density[idx0]  :  0.f;
    float d1  = v1 ? g_density[idx1]  :  0.f;
    float sg0 = v0 ? d0 * g_init[b*M_PTS + idx0] : 0.f;
    float sg1 = v1 ? d1 * g_init[b*M_PTS + idx1] : 0.f;
    float nd0 = -d0, nd1 = -d1;
    __syncthreads();

    float* myrow = &tile[tid*TSTR];
    int rg = tid >> 4;            // 0..7 (row groups, rows rg+8i)
    int cg = tid & 15;            // 0..15 (4-col groups)
    float* gout = &g_bpart[((size_t)b*NTILES + blockIdx.x)*TT];

    for (int c0 = 0; c0 < TT; c0 += TC) {
#pragma unroll 2
        for (int t4 = 0; t4 < TC; t4 += 4) {
            float4 h4 = *(const float4*)&sh_h[c0 + t4];
            float o[4];
            float hts[4] = {h4.x, h4.y, h4.z, h4.w};
#pragma unroll
            for (int u = 0; u < 4; u++) {
                float ht = hts[u];
                float xu  = ht - al;
                float xd0 = be0 - ht;
                float xd1 = be1 - ht;
                bool nearany = (fabsf(xu) < CUT) | (fabsf(xd0) < CUT) | (fabsf(xd1) < CUT);
                if (__any_sync(0xffffffffu, nearany)) {
                    float wu  = 0.5f*fast_tanh(500.f*xu)  + 0.5f;
                    float wd0 = 0.5f*fast_tanh(500.f*xd0) + 0.5f;
                    float wd1 = 0.5f*fast_tanh(500.f*xd1) + 0.5f;
                    sg0 += wu  * (d0  - sg0);
                    sg1 += wu  * (d1  - sg1);
                    sg0 += wd0 * (nd0 - sg0);
                    sg1 += wd1 * (nd1 - sg1);
                } else {
                    if (xu  > 0.f) { sg0 = d0; sg1 = d1; }
                    if (xd0 > 0.f) sg0 = nd0;
                    if (xd1 > 0.f) sg1 = nd1;
                }
                o[u] = sg0 + sg1;
            }
            *(float4*)&myrow[t4] = make_float4(o[0], o[1], o[2], o[3]);
        }
        __syncthreads();
        // reduce 128 rows x 64 cols: thread sums 16 rows (rg+8i) x 4 cols
        float4 s4 = make_float4(0.f, 0.f, 0.f, 0.f);
#pragma unroll
        for (int i = 0; i < 16; i++) {
            float4 v = *(const float4*)&tile[(rg + 8*i)*TSTR + cg*4];
            s4.x += v.x; s4.y += v.y; s4.z += v.z; s4.w += v.w;
        }
        *(float4*)&aux[rg*TSTR + cg*4] = s4;
        __syncthreads();
        if (tid < TC) {
            float a = 0.f;
#pragma unroll
            for (int g = 0; g < 8; g++) a += aux[g*TSTR + tid];
            gout[c0 + tid] = a;
        }
        __syncthreads();
    }
}

// ---------------- final ----------------
__global__ void k_final(const float* __restrict__ dec,
                        const float* __restrict__ hraw,
                        const float* __restrict__ mraw,
                        const float* __restrict__ oraw,
                        float* __restrict__ out) {
    __shared__ float sred[256];
    int tid = threadIdx.x;
    float a = 0.f;
    for (int i = tid; i < M_PTS; i += 256) a += g_density[i];
    sred[tid] = a;
    __syncthreads();
    for (int o = 128; o; o >>= 1) {
        if (tid < o) sred[tid] += sred[tid + o];
        __syncthreads();
    }
    float dsum = sred[0];

    int i = blockIdx.x*256 + tid;
    int b = i >> 10, t = i & 1023;
    float acc = 0.f;
#pragma unroll
    for (int k = 0; k < NTILES; k++)
        acc += g_bpart[((size_t)b*NTILES + k)*TT + t];
    float mv = acc / dsum;
    float h = dec[i];
    float hs  = 10.f / (1.f + __expf(-hraw[0]));
    float ms  = 10.f / (1.f + __expf(-mraw[0]));
    float off = -10.f + 20.f / (1.f + __expf(-oraw[0]));
    out[OFF_BOUT + i] = hs*h + ms*mv + off;
    out[OFF_M + i] = mv;
}

// ---------------- launch ----------------
extern "C" void kernel_launch(void* const* d_in, const int* in_sizes, int n_in,
                              void* d_out, int out_size) {
    (void)in_sizes; (void)n_in; (void)out_size;
    const float* enc   = (const float*)d_in[0];
    const float* dec   = (const float*)d_in[1];
    const float* msk   = (const float*)d_in[2];
    const float* mesh  = (const float*)d_in[3];
    const float* dWin  = (const float*)d_in[4];
    const float* dbin  = (const float*)d_in[5];
    const float* dWr   = (const float*)d_in[6];
    const float* dbr   = (const float*)d_in[7];
    const float* dWout = (const float*)d_in[8];
    const float* dbout = (const float*)d_in[9];
    const float* eWs   = (const float*)d_in[10];
    const float* ebs   = (const float*)d_in[11];
    const float* eWm   = (const float*)d_in[12];
    const float* eWc   = (const float*)d_in[13];
    const float* ebm   = (const float*)d_in[14];
    const float* eWo   = (const float*)d_in[15];
    const float* ebo   = (const float*)d_in[16];
    const float* hraw  = (const float*)d_in[17];
    const float* mraw  = (const float*)d_in[18];
    const float* oraw  = (const float*)d_in[19];
    float* out = (float*)d_out;

    static int smem_set = 0;
    if (!smem_set) {
        cudaFuncSetAttribute(k_mlp, cudaFuncAttributeMaxDynamicSharedMemorySize,
                             MLP_SMEM_BYTES);
        smem_set = 1;
    }

    // W split/pack + fused density MLP
    k_wsplitp<<<384, 256>>>(dWr);
    k_mlp<<<161, 256, MLP_SMEM_BYTES>>>(mesh, dWin, dbin, dbr, dWout, dbout);

    // encoder + initial states (batch-major)
    k_ctxw<<<BB, 256>>>(enc, msk, eWs, ebs, eWc);
    k_init<<<161, 256>>>(mesh, eWm, ebm, eWo, ebo, out);

    // relay scan + final
    dim3 gscan(NTILES, BB);
    k_scan<<<gscan, 128>>>(dec, mesh);
    k_final<<<64, 256>>>(dec, hraw, mraw, oraw, out);
}

// round 15
// speedup vs baseline: 1.0237x; 1.0237x over previous
#include <cuda_runtime.h>
#include <cstdint>

#define M_PTS 5151
#define HIDN  256
#define BB    16
#define SS    256
#define TT    1024
#define GRID_N 101
#define TDIM   16
#define NTILES 28          // 7x7 upper-triangular tiles of 16x16
#define TC     64          // scan time-chunk
#define TSTR   68          // tile row stride (floats, 16B aligned)
#define CUT 0.018f

// k_mlp smem (words): Xh_p/Xl_p 32x132 uint32 each; Bh_p/Bl_p 8x264 each
#define XP_STR 132
#define BP_STR 264
#define SM_XH 0
#define SM_XL (32*XP_STR)
#define SM_BH (2*32*XP_STR)
#define SM_BL (2*32*XP_STR + 8*BP_STR)
#define MLP_SMEM_WORDS (2*32*XP_STR + 2*8*BP_STR)
#define MLP_SMEM_BYTES (MLP_SMEM_WORDS*4)           // 50688

#define OFF_BOUT 0
#define OFF_D    16384
#define OFF_M    (OFF_D + BB*M_PTS)
#define OFF_IS   (OFF_M + BB*TT)
#define OFF_MESH (OFF_IS + BB*M_PTS)

// ---------------- scratch ----------------
__device__ uint32_t g_wph[3*128*HIDN];
__device__ uint32_t g_wpl[3*128*HIDN];
__device__ float g_density[M_PTS];
__device__ float g_cwc[BB*HIDN];
__device__ float g_init[BB*M_PTS];
__device__ float g_bpart[BB*NTILES*TT];

__device__ __forceinline__ float fast_tanh(float x) {
    float r;
    asm("tanh.approx.f32 %0, %1;" : "=f"(r) : "f"(x));
    return r;
}

__device__ __forceinline__ float bf16lo_f(uint32_t p) {
    return __uint_as_float(p << 16);
}
__device__ __forceinline__ float bf16hi_f(uint32_t p) {
    return __uint_as_float(p & 0xffff0000u);
}
__device__ __forceinline__ uint32_t pack_split(float x0, float x1, uint32_t* lo) {
    uint32_t hp;
    asm("cvt.rn.bf16x2.f32 %0, %1, %2;" : "=r"(hp) : "f"(x1), "f"(x0));
    float h0 = bf16lo_f(hp), h1 = bf16hi_f(hp);
    uint32_t lp;
    asm("cvt.rn.bf16x2.f32 %0, %1, %2;" : "=r"(lp) : "f"(x1 - h1), "f"(x0 - h0));
    *lo = lp;
    return hp;
}

__device__ __forceinline__ void mma_bf16(float* c, const uint32_t* a, const uint32_t* b) {
    asm volatile(
        "mma.sync.aligned.m16n8k16.row.col.f32.bf16.bf16.f32 "
        "{%0,%1,%2,%3}, {%4,%5,%6,%7}, {%8,%9}, {%0,%1,%2,%3};"
        : "+f"(c[0]), "+f"(c[1]), "+f"(c[2]), "+f"(c[3])
        : "r"(a[0]), "r"(a[1]), "r"(a[2]), "r"(a[3]),
          "r"(b[0]), "r"(b[1]));
}

// ---------------- W split+pack (once) ----------------
__global__ void k_wsplitp(const float* __restrict__ Wr) {
    int i = blockIdx.x*256 + threadIdx.x;
    if (i >= 3*128*HIDN) return;
    int l  = i >> 15;
    int r2 = (i >> 8) & 127;
    int n  = i & 255;
    const float* base = Wr + l*HIDN*HIDN;
    float w0 = base[(2*r2  )*HIDN + n];
    float w1 = base[(2*r2+1)*HIDN + n];
    uint32_t lo;
    uint32_t hi = pack_split(w0, w1, &lo);
    g_wph[i] = hi;
    g_wpl[i] = lo;
}

// ===== fused density MLP: dens_in + 3 res layers (bf16 3-term) + dens_out ==
__global__ void __launch_bounds__(256) k_mlp(
    const float* __restrict__ mesh,
    const float* __restrict__ Win, const float* __restrict__ bin,
    const float* __restrict__ br,
    const float* __restrict__ Wout, const float* __restrict__ bout)
{
    extern __shared__ __align__(16) uint32_t smw[];
    uint32_t* Xh = smw + SM_XH;
    uint32_t* Xl = smw + SM_XL;
    uint32_t* Bh = smw + SM_BH;
    uint32_t* Bl = smw + SM_BL;

    int tid = threadIdx.x;
    int bm = blockIdx.x * 32;

    {
        int r  = tid >> 3;
        int c0 = (tid & 7) * 32;
        int gr = bm + r;
        bool ok = gr < M_PTS;
        float be = ok ? mesh[2*gr]   : 0.f;
        float al = ok ? mesh[2*gr+1] : 0.f;
#pragma unroll 4
        for (int p = 0; p < 16; p++) {
            int c = c0 + 2*p;
            float x0 = ok ? fmaxf(be*Win[c]   + al*Win[HIDN+c]   + bin[c],   0.f) : 0.f;
            float x1 = ok ? fmaxf(be*Win[c+1] + al*Win[HIDN+c+1] + bin[c+1], 0.f) : 0.f;
            uint32_t lo;
            uint32_t hi = pack_split(x0, x1, &lo);
            Xh[r*XP_STR + (c>>1)] = hi;
            Xl[r*XP_STR + (c>>1)] = lo;
        }
    }
    __syncthreads();

    int warp = tid >> 5, lane = tid & 31;
    int lr = lane >> 2, lc = lane & 3;
    int n_base = warp * 32;

    int woff = tid * 8;
    int wr2  = woff >> 8;
    int wcc  = woff & 255;

    for (int layer = 0; layer < 3; layer++) {
        const uint32_t* WPH = g_wph + layer*128*HIDN;
        const uint32_t* WPL = g_wpl + layer*128*HIDN;
        const float* bias = br + layer*HIDN;

        float acc[2][4][4];
#pragma unroll
        for (int t = 0; t < 2; t++)
#pragma unroll
            for (int j = 0; j < 4; j++)
#pragma unroll
                for (int q = 0; q < 4; q++) acc[t][j][q] = 0.f;

        uint4 ph0 = *(const uint4*)&WPH[woff];
        uint4 ph1 = *(const uint4*)&WPH[woff + 4];
        uint4 pl0 = *(const uint4*)&WPL[woff];
        uint4 pl1 = *(const uint4*)&WPL[woff + 4];

        for (int ch = 0; ch < 16; ch++) {
            *(uint4*)&Bh[wr2*BP_STR + wcc]     = ph0;
            *(uint4*)&Bh[wr2*BP_STR + wcc + 4] = ph1;
            *(uint4*)&Bl[wr2*BP_STR + wcc]     = pl0;
            *(uint4*)&Bl[wr2*BP_STR + wcc + 4] = pl1;
            __syncthreads();

            if (ch < 15) {
                int g = (ch + 1)*2048 + woff;
                ph0 = *(const uint4*)&WPH[g];
                ph1 = *(const uint4*)&WPH[g + 4];
                pl0 = *(const uint4*)&WPL[g];
                pl1 = *(const uint4*)&WPL[g + 4];
            }

            int k2b = ch * 8;
            uint32_t a_h[2][4], a_l[2][4];
#pragma unroll
            for (int t = 0; t < 2; t++) {
                int r = t*16 + lr;
                a_h[t][0] = Xh[ r     *XP_STR + k2b + lc];
                a_h[t][1] = Xh[(r + 8)*XP_STR + k2b + lc];
                a_h[t][2] = Xh[ r     *XP_STR + k2b + lc + 4];
                a_h[t][3] = Xh[(r + 8)*XP_STR + k2b + lc + 4];
                a_l[t][0] = Xl[ r     *XP_STR + k2b + lc];
                a_l[t][1] = Xl[(r + 8)*XP_STR + k2b + lc];
                a_l[t][2] = Xl[ r     *XP_STR + k2b + lc + 4];
                a_l[t][3] = Xl[(r + 8)*XP_STR + k2b + lc + 4];
            }
            uint32_t b_h[4][2], b_l[4][2];
#pragma unroll
            for (int j = 0; j < 4; j++) {
                int n = n_base + j*8 + lr;
                b_h[j][0] = Bh[ lc     *BP_STR + n];
                b_h[j][1] = Bh[(lc + 4)*BP_STR + n];
                b_l[j][0] = Bl[ lc     *BP_STR + n];
                b_l[j][1] = Bl[(lc + 4)*BP_STR + n];
            }
#pragma unroll
            for (int t = 0; t < 2; t++)
#pragma unroll
                for (int j = 0; j < 4; j++) {
                    mma_bf16(acc[t][j], a_h[t], b_h[j]);
                    mma_bf16(acc[t][j], a_h[t], b_l[j]);
                    mma_bf16(acc[t][j], a_l[t], b_h[j]);
                }
            __syncthreads();
        }

#pragma unroll
        for (int t = 0; t < 2; t++)
#pragma unroll
            for (int j = 0; j < 4; j++) {
                int c = n_base + j*8 + 2*lc;
                int c2 = c >> 1;
                float2 bz = *(const float2*)&bias[c];
#pragma unroll
                for (int h = 0; h < 2; h++) {
                    int r = t*16 + lr + 8*h;
                    int g = r*XP_STR + c2;
                    uint32_t hp = Xh[g], lp = Xl[g];
                    float x0 = bf16lo_f(hp) + bf16lo_f(lp);
                    float x1 = bf16hi_f(hp) + bf16hi_f(lp);
                    float y0 = x0 + fmaxf(acc[t][j][2*h]   + bz.x, 0.f);
                    float y1 = x1 + fmaxf(acc[t][j][2*h+1] + bz.y, 0.f);
                    uint32_t lo;
                    Xh[g] = pack_split(y0, y1, &lo);
                    Xl[g] = lo;
                }
            }
        __syncthreads();
    }

    {
        float b0 = bout[0];
#pragma unroll
        for (int rr = 0; rr < 4; rr++) {
            int r = warp*4 + rr;
            int gr = bm + r;
            float a = 0.f;
#pragma unroll
            for (int i = 0; i < 4; i++) {
                int c2 = lane + i*32;
                uint32_t hp = Xh[r*XP_STR + c2], lp = Xl[r*XP_STR + c2];
                a += (bf16lo_f(hp) + bf16lo_f(lp)) * Wout[2*c2];
                a += (bf16hi_f(hp) + bf16hi_f(lp)) * Wout[2*c2+1];
            }
#pragma unroll
            for (int o = 16; o; o >>= 1) a += __shfl_xor_sync(0xffffffffu, a, o);
            if (lane == 0 && gr < M_PTS)
                g_density[gr] = 1.f / (1.f + __expf(-(a + b0)));
        }
    }
}

// ---------------- encoder ctx + ctx @ Wc ----------------
__global__ void k_ctxw(const float* __restrict__ enc,
                       const float* __restrict__ mask,
                       const float* __restrict__ Ws,
                       const float* __restrict__ bs,
                       const float* __restrict__ Wc) {
    int b = blockIdx.x;
    int j = threadIdx.x;
    __shared__ float se[2*SS];
    __shared__ float sm[SS];
    __shared__ float sctx[HIDN];
    for (int i = j; i < 2*SS; i += 256) se[i] = enc[b*2*SS + i];
    for (int i = j; i < SS;   i += 256) sm[i] = mask[b*SS + i];
    __syncthreads();
    float w0 = Ws[j], w1 = Ws[HIDN + j], bj = bs[j];
    float acc = 0.f, msum = 0.f;
    for (int s = 0; s < SS; s++) {
        float mk = sm[s];
        msum += mk;
        float v = fmaxf(se[2*s]*w0 + se[2*s+1]*w1 + bj, 0.f);
        acc += mk * v;
    }
    sctx[j] = acc / fmaxf(msum, 1.f);
    __syncthreads();
    float a2 = 0.f;
    for (int k = 0; k < HIDN; k++) a2 += sctx[k] * Wc[k*HIDN + j];
    g_cwc[b*HIDN + j] = a2;
}

// ------- initial states, batch-major v3: 16 m-points x 16 strips ---------
// grid 322; thread = (ml 0..15, strip 0..15); j = strip + 16*jj.
__global__ void __launch_bounds__(256) k_init(
    const float* __restrict__ mesh,
    const float* __restrict__ Wm,
    const float* __restrict__ bm,
    const float* __restrict__ Wo,
    const float* __restrict__ bo,
    float* __restrict__ out)
{
    __shared__ __align__(16) float4 sW[HIDN];        // (w0,w1,w2,wo)
    __shared__ float sC[BB*HIDN];                    // cwc + bm
    int tid = threadIdx.x;

    {
        sW[tid] = make_float4(Wm[tid], Wm[HIDN + tid], Wm[2*HIDN + tid], Wo[tid]);
        float bmj = bm[tid];
#pragma unroll
        for (int b = 0; b < BB; b++)
            sC[b*HIDN + tid] = g_cwc[b*HIDN + tid] + bmj;
    }
    __syncthreads();

    int ml = tid >> 4;            // 0..15
    int strip = tid & 15;         // 0..15
    int m = blockIdx.x*16 + ml;
    bool ok = m < M_PTS;
    int mm = ok ? m : 0;
    float be = mesh[2*mm], al = mesh[2*mm+1], d = g_density[mm];

    float acc[BB];
#pragma unroll
    for (int b = 0; b < BB; b++) acc[b] = 0.f;

#pragma unroll 4
    for (int jj = 0; jj < 16; jj++) {
        int j = strip + 16*jj;
        float4 w = sW[j];
        float P = be*w.x + al*w.y + d*w.z;
        float wo = w.w;
#pragma unroll
        for (int b = 0; b < BB; b++)
            acc[b] += fmaxf(P + sC[b*HIDN + j], 0.f) * wo;
    }

    // reduce across the 16 strips (contiguous lanes)
#pragma unroll
    for (int b = 0; b < BB; b++) {
        acc[b] += __shfl_xor_sync(0xffffffffu, acc[b], 1);
        acc[b] += __shfl_xor_sync(0xffffffffu, acc[b], 2);
        acc[b] += __shfl_xor_sync(0xffffffffu, acc[b], 4);
        acc[b] += __shfl_xor_sync(0xffffffffu, acc[b], 8);
    }

    if (strip == 0 && ok) {
        float bo0 = bo[0];
#pragma unroll
        for (int b = 0; b < BB; b++) {
            float is = tanhf(acc[b] + bo0);
            g_init[b*M_PTS + m] = is;
            out[OFF_IS + (size_t)b*M_PTS + m] = is;
            out[OFF_D  + (size_t)b*M_PTS + m] = d;
            ((float2*)out)[(OFF_MESH >> 1) + (size_t)b*M_PTS + m] = make_float2(be, al);
        }
    }
}

// ------- relay scan: 16beta x 16alpha tiles, 128 thr, 2 beta pts/thread ---
__global__ void __launch_bounds__(128) k_scan(const float* __restrict__ dec,
                                              const float* __restrict__ mesh) {
    __shared__ __align__(16) float sh_h[TT];
    __shared__ __align__(16) float tile[128*TSTR];
    __shared__ __align__(16) float aux[8*TSTR];
    int b = blockIdx.y;
    int tid = threadIdx.x;        // 0..127

    int tb = 0, rem = blockIdx.x;
    while (rem >= 7 - tb) { rem -= 7 - tb; tb++; }
    int ta = tb + rem;

    int ib0 = tb*TDIM + 2*(tid >> 4);
    int ib1 = ib0 + 1;
    int ia  = ta*TDIM + (tid & 15);
    bool v0 = (ib0 <= ia) && (ib0 < GRID_N) && (ia < GRID_N);
    bool v1 = (ib1 <= ia) && (ib1 < GRID_N) && (ia < GRID_N);
    int idx0 = v0 ? (ib0*GRID_N - (ib0*(ib0-1))/2 + ia - ib0) : 0;
    int idx1 = v1 ? (ib1*GRID_N - (ib1*(ib1-1))/2 + ia - ib1) : 0;

    for (int t = tid; t < TT; t += 128) sh_h[t] = dec[b*TT + t];

    float al  = v0 ? mesh[2*idx0 + 1] : (v1 ? mesh[2*idx1 + 1] : 2.f);
    float be0 = v0 ? mesh[2*idx0]     : -2.f;
    float be1 = v1 ? mesh[2*idx1]     : -2.f;
    float d0  = v0 ? g_density[idx0]  :  0.f;
    float d1  = v1 ? g_density[idx1]  :  0.f;
    float sg0 = v0 ? d0 * g_init[b*M_PTS + idx0] : 0.f;
    float sg1 = v1 ? d1 * g_init[b*M_PTS + idx1] : 0.f;
    float nd0 = -d0, nd1 = -d1;
    __syncthreads();

    float* myrow = &tile[tid*TSTR];
    int rg = tid >> 4;            // 0..7
    int cg = tid & 15;            // 0..15
    float* gout = &g_bpart[((size_t)b*NTILES + blockIdx.x)*TT];

    for (int c0 = 0; c0 < TT; c0 += TC) {
#pragma unroll 2
        for (int t4 = 0; t4 < TC; t4 += 4) {
            float4 h4 = *(const float4*)&sh_h[c0 + t4];
            float o[4];
            float hts[4] = {h4.x, h4.y, h4.z, h4.w};
#pragma unroll
            for (int u = 0; u < 4; u++) {
                float ht = hts[u];
                float xu  = ht - al;
                float xd0 = be0 - ht;
                float xd1 = be1 - ht;
                bool nearany = (fabsf(xu) < CUT) | (fabsf(xd0) < CUT) | (fabsf(xd1) < CUT);
                if (__any_sync(0xffffffffu, nearany)) {
                    float wu  = 0.5f*fast_tanh(500.f*xu)  + 0.5f;
                    float wd0 = 0.5f*fast_tanh(500.f*xd0) + 0.5f;
                    float wd1 = 0.5f*fast_tanh(500.f*xd1) + 0.5f;
                    sg0 += wu  * (d0  - sg0);
                    sg1 += wu  * (d1  - sg1);
                    sg0 += wd0 * (nd0 - sg0);
                    sg1 += wd1 * (nd1 - sg1);
                } else {
                    if (xu  > 0.f) { sg0 = d0; sg1 = d1; }
                    if (xd0 > 0.f) sg0 = nd0;
                    if (xd1 > 0.f) sg1 = nd1;
                }
                o[u] = sg0 + sg1;
            }
            *(float4*)&myrow[t4] = make_float4(o[0], o[1], o[2], o[3]);
        }
        __syncthreads();
        float4 s4 = make_float4(0.f, 0.f, 0.f, 0.f);
#pragma unroll
        for (int i = 0; i < 16; i++) {
            float4 v = *(const float4*)&tile[(rg + 8*i)*TSTR + cg*4];
            s4.x += v.x; s4.y += v.y; s4.z += v.z; s4.w += v.w;
        }
        *(float4*)&aux[rg*TSTR + cg*4] = s4;
        __syncthreads();
        if (tid < TC) {
            float a = 0.f;
#pragma unroll
            for (int g = 0; g < 8; g++) a += aux[g*TSTR + tid];
            gout[c0 + tid] = a;
        }
        __syncthreads();
    }
}

// ---------------- final ----------------
__global__ void k_final(const float* __restrict__ dec,
                        const float* __restrict__ hraw,
                        const float* __restrict__ mraw,
                        const float* __restrict__ oraw,
                        float* __restrict__ out) {
    __shared__ float sred[256];
    int tid = threadIdx.x;
    float a = 0.f;
    for (int i = tid; i < M_PTS; i += 256) a += g_density[i];
    sred[tid] = a;
    __syncthreads();
    for (int o = 128; o; o >>= 1) {
        if (tid < o) sred[tid] += sred[tid + o];
        __syncthreads();
    }
    float dsum = sred[0];

    int i = blockIdx.x*256 + tid;
    int b = i >> 10, t = i & 1023;
    float acc = 0.f;
#pragma unroll
    for (int k = 0; k < NTILES; k++)
        acc += g_bpart[((size_t)b*NTILES + k)*TT + t];
    float mv = acc / dsum;
    float h = dec[i];
    float hs  = 10.f / (1.f + __expf(-hraw[0]));
    float ms  = 10.f / (1.f + __expf(-mraw[0]));
    float off = -10.f + 20.f / (1.f + __expf(-oraw[0]));
    out[OFF_BOUT + i] = hs*h + ms*mv + off;
    out[OFF_M + i] = mv;
}

// ---------------- launch ----------------
extern "C" void kernel_launch(void* const* d_in, const int* in_sizes, int n_in,
                              void* d_out, int out_size) {
    (void)in_sizes; (void)n_in; (void)out_size;
    const float* enc   = (const float*)d_in[0];
    const float* dec   = (const float*)d_in[1];
    const float* msk   = (const float*)d_in[2];
    const float* mesh  = (const float*)d_in[3];
    const float* dWin  = (const float*)d_in[4];
    const float* dbin  = (const float*)d_in[5];
    const float* dWr   = (const float*)d_in[6];
    const float* dbr   = (const float*)d_in[7];
    const float* dWout = (const float*)d_in[8];
    const float* dbout = (const float*)d_in[9];
    const float* eWs   = (const float*)d_in[10];
    const float* ebs   = (const float*)d_in[11];
    const float* eWm   = (const float*)d_in[12];
    const float* eWc   = (const float*)d_in[13];
    const float* ebm   = (const float*)d_in[14];
    const float* eWo   = (const float*)d_in[15];
    const float* ebo   = (const float*)d_in[16];
    const float* hraw  = (const float*)d_in[17];
    const float* mraw  = (const float*)d_in[18];
    const float* oraw  = (const float*)d_in[19];
    float* out = (float*)d_out;

    static int smem_set = 0;
    if (!smem_set) {
        cudaFuncSetAttribute(k_mlp, cudaFuncAttributeMaxDynamicSharedMemorySize,
                             MLP_SMEM_BYTES);
        smem_set = 1;
    }

    // W split/pack + fused density MLP
    k_wsplitp<<<384, 256>>>(dWr);
    k_mlp<<<161, 256, MLP_SMEM_BYTES>>>(mesh, dWin, dbin, dbr, dWout, dbout);

    // encoder + initial states (batch-major, 16 m/block)
    k_ctxw<<<BB, 256>>>(enc, msk, eWs, ebs, eWc);
    k_init<<<322, 256>>>(mesh, eWm, ebm, eWo, ebo, out);

    // relay scan + final
    dim3 gscan(NTILES, BB);
    k_scan<<<gscan, 128>>>(dec, mesh);
    k_final<<<64, 256>>>(dec, hraw, mraw, oraw, out);
}